// round 3
// baseline (speedup 1.0000x reference)
#include <cuda_runtime.h>
#include <cstdint>

#define T 32
#define NN 10000
#define DEG 32
#define ROWS (T*NN)          // 320000
#define HEADS 4
#define H1 32
#define H2 32
#define GRUD 32
#define PH 5

// ---------------- scratch (device globals; no allocation allowed) ----------
__device__ float g_z1[(size_t)ROWS * 128];   // [row][hd*32+e]
__device__ float g_s1a[ROWS * 4];            // a_src . z1  per (row, head)
__device__ float g_s2a[ROWS * 4];            // a_dst . z1
__device__ float g_h1[(size_t)ROWS * 128];   // relu(agg1), head-major feats
__device__ float g_z2[(size_t)ROWS * 32];
__device__ float g_s1b[ROWS];
__device__ float g_s2b[ROWS];
__device__ float g_cur[T * 32];              // per-t feature max (>=0)

__global__ void zero_cur_kernel() {
    g_cur[threadIdx.x] = 0.0f;               // 1024 threads = T*32
}

// ---------------- GEMM1: z1 = h @ W1 (per-head), + attention score scalars --
// A: (ROWS,128), B: 128x128 (cols j = hd*32+e). BM=128, BN=128, BK=32,
// 256 threads, 8x8 micro-tile.
__global__ __launch_bounds__(256) void gemm1_kernel(
    const float* __restrict__ A, const float* __restrict__ W1,
    const float* __restrict__ a1)
{
    __shared__ float Ash[32][132];   // [k][m], padded
    __shared__ float Bsh[32][128];   // [k][j]
    int tid = threadIdx.x;
    int tx = tid & 15, ty = tid >> 4;
    int rowBase = blockIdx.x * 128;

    float c[8][8];
#pragma unroll
    for (int i = 0; i < 8; i++)
#pragma unroll
        for (int j = 0; j < 8; j++) c[i][j] = 0.0f;

    int kq = (tid & 7) * 4;
    int mrow = tid >> 3;             // 0..31

    for (int kb = 0; kb < 4; kb++) {
        // A tile (transposed into shared)
#pragma unroll
        for (int m0 = 0; m0 < 128; m0 += 32) {
            float4 v = *(const float4*)(A + (size_t)(rowBase + m0 + mrow) * 128 + kb * 32 + kq);
            Ash[kq + 0][m0 + mrow] = v.x;
            Ash[kq + 1][m0 + mrow] = v.y;
            Ash[kq + 2][m0 + mrow] = v.z;
            Ash[kq + 3][m0 + mrow] = v.w;
        }
        // B tile: Bsh[k][j] = W1[j>>5][kb*32+k][j&31]
#pragma unroll
        for (int f = 0; f < 4; f++) {
            int id4 = f * 256 + tid;         // 0..1023
            int k = id4 >> 5;
            int j4 = (id4 & 31) * 4;
            float4 v = *(const float4*)(W1 + (j4 >> 5) * 4096 + (kb * 32 + k) * 32 + (j4 & 31));
            *(float4*)&Bsh[k][j4] = v;
        }
        __syncthreads();
#pragma unroll
        for (int k = 0; k < 32; k++) {
            float af[8], bf[8];
            *(float4*)(af)     = *(float4*)&Ash[k][ty * 8];
            *(float4*)(af + 4) = *(float4*)&Ash[k][ty * 8 + 4];
            *(float4*)(bf)     = *(float4*)&Bsh[k][tx * 8];
            *(float4*)(bf + 4) = *(float4*)&Bsh[k][tx * 8 + 4];
#pragma unroll
            for (int mi = 0; mi < 8; mi++)
#pragma unroll
                for (int ji = 0; ji < 8; ji++)
                    c[mi][ji] += af[mi] * bf[ji];
        }
        __syncthreads();
    }

    // epilogue: write z1 + head-score partials
    int hd = tx >> 2;
    int e0 = (tx & 3) * 8;
    float w1v[8], w2v[8];
#pragma unroll
    for (int ji = 0; ji < 8; ji++) {
        w1v[ji] = a1[hd * 64 + e0 + ji];
        w2v[ji] = a1[hd * 64 + 32 + e0 + ji];
    }
#pragma unroll
    for (int mi = 0; mi < 8; mi++) {
        size_t row = (size_t)rowBase + ty * 8 + mi;
        float4 v0 = make_float4(c[mi][0], c[mi][1], c[mi][2], c[mi][3]);
        float4 v1 = make_float4(c[mi][4], c[mi][5], c[mi][6], c[mi][7]);
        *(float4*)(g_z1 + row * 128 + tx * 8)     = v0;
        *(float4*)(g_z1 + row * 128 + tx * 8 + 4) = v1;
        float p1 = 0.f, p2 = 0.f;
#pragma unroll
        for (int ji = 0; ji < 8; ji++) { p1 += c[mi][ji] * w1v[ji]; p2 += c[mi][ji] * w2v[ji]; }
        p1 += __shfl_xor_sync(0xffffffffu, p1, 1);
        p1 += __shfl_xor_sync(0xffffffffu, p1, 2);
        p2 += __shfl_xor_sync(0xffffffffu, p2, 1);
        p2 += __shfl_xor_sync(0xffffffffu, p2, 2);
        if ((tx & 3) == 0) {
            g_s1a[row * 4 + hd] = p1;
            g_s2a[row * 4 + hd] = p2;
        }
    }
}

// ---------------- agg1: softmax over neighbors + weighted gather, relu -----
// warp per (t,n,head); 8 warps/block; blocksPerT = 40000/8 = 5000
__global__ __launch_bounds__(256) void agg1_kernel(const int* __restrict__ src)
{
    int warp = threadIdx.x >> 5, lane = threadIdx.x & 31;
    int t = blockIdx.x / 5000;
    int id = (blockIdx.x % 5000) * 8 + warp;   // 0..39999
    int n = id >> 2, hd = id & 3;
    int rowbase = t * NN;

    int sd = src[n * 32 + lane];
    float e = g_s1a[(size_t)(rowbase + sd) * 4 + hd] + g_s2a[(size_t)(rowbase + n) * 4 + hd];
    e = (e > 0.f) ? e : 0.01f * e;          // leaky_relu(0.01)
    float m = e;
#pragma unroll
    for (int o = 16; o; o >>= 1) m = fmaxf(m, __shfl_xor_sync(0xffffffffu, m, o));
    float p = expf(e - m);
    float sum = p;
#pragma unroll
    for (int o = 16; o; o >>= 1) sum += __shfl_xor_sync(0xffffffffu, sum, o);
    float alpha = p / sum;

    const float* zb = g_z1 + (size_t)rowbase * 128 + hd * 32;
    float acc = 0.f;
#pragma unroll
    for (int d = 0; d < 32; d++) {
        float a = __shfl_sync(0xffffffffu, alpha, d);
        int s = __shfl_sync(0xffffffffu, sd, d);
        acc += a * zb[(size_t)s * 128 + lane];
    }
    g_h1[(size_t)(rowbase + n) * 128 + hd * 32 + lane] = fmaxf(acc, 0.f);
}

// ---------------- GEMM2: z2 = h1 @ W2 (128->32) + score scalars ------------
// BM=128, BN=32, BK=32, 256 threads, 4x4 micro-tile.
__global__ __launch_bounds__(256) void gemm2_kernel(
    const float* __restrict__ W2, const float* __restrict__ a2)
{
    __shared__ float Ash[32][132];
    __shared__ float Bsh[32][32];
    int tid = threadIdx.x;
    int tx = tid & 7, ty = tid >> 3;    // ty 0..31
    int rowBase = blockIdx.x * 128;

    float c[4][4];
#pragma unroll
    for (int i = 0; i < 4; i++)
#pragma unroll
        for (int j = 0; j < 4; j++) c[i][j] = 0.0f;

    int kq = (tid & 7) * 4;
    int mrow = tid >> 3;

    for (int kb = 0; kb < 4; kb++) {
#pragma unroll
        for (int m0 = 0; m0 < 128; m0 += 32) {
            float4 v = *(const float4*)(g_h1 + (size_t)(rowBase + m0 + mrow) * 128 + kb * 32 + kq);
            Ash[kq + 0][m0 + mrow] = v.x;
            Ash[kq + 1][m0 + mrow] = v.y;
            Ash[kq + 2][m0 + mrow] = v.z;
            Ash[kq + 3][m0 + mrow] = v.w;
        }
        {
            int k = tid >> 3, j4 = (tid & 7) * 4;   // 256 threads cover 32x32
            *(float4*)&Bsh[k][j4] = *(const float4*)(W2 + (kb * 32 + k) * 32 + j4);
        }
        __syncthreads();
#pragma unroll
        for (int k = 0; k < 32; k++) {
            float af[4], bf[4];
            *(float4*)af = *(float4*)&Ash[k][ty * 4];
            *(float4*)bf = *(float4*)&Bsh[k][tx * 4];
#pragma unroll
            for (int mi = 0; mi < 4; mi++)
#pragma unroll
                for (int ji = 0; ji < 4; ji++)
                    c[mi][ji] += af[mi] * bf[ji];
        }
        __syncthreads();
    }

    float w1v[4], w2v[4];
#pragma unroll
    for (int ji = 0; ji < 4; ji++) {
        w1v[ji] = a2[tx * 4 + ji];
        w2v[ji] = a2[32 + tx * 4 + ji];
    }
#pragma unroll
    for (int mi = 0; mi < 4; mi++) {
        size_t row = (size_t)rowBase + ty * 4 + mi;
        *(float4*)(g_z2 + row * 32 + tx * 4) =
            make_float4(c[mi][0], c[mi][1], c[mi][2], c[mi][3]);
        float p1 = 0.f, p2 = 0.f;
#pragma unroll
        for (int ji = 0; ji < 4; ji++) { p1 += c[mi][ji] * w1v[ji]; p2 += c[mi][ji] * w2v[ji]; }
        p1 += __shfl_xor_sync(0xffffffffu, p1, 1);
        p1 += __shfl_xor_sync(0xffffffffu, p1, 2);
        p1 += __shfl_xor_sync(0xffffffffu, p1, 4);
        p2 += __shfl_xor_sync(0xffffffffu, p2, 1);
        p2 += __shfl_xor_sync(0xffffffffu, p2, 2);
        p2 += __shfl_xor_sync(0xffffffffu, p2, 4);
        if (tx == 0) { g_s1b[row] = p1; g_s2b[row] = p2; }
    }
}

// ---------------- agg2: softmax gather + relu + node-max into g_cur --------
// warp per (t,n); blocksPerT = 10000/8 = 1250
__global__ __launch_bounds__(256) void agg2_kernel(const int* __restrict__ src)
{
    __shared__ unsigned smax[32];
    int warp = threadIdx.x >> 5, lane = threadIdx.x & 31;
    int t = blockIdx.x / 1250;
    int n = (blockIdx.x % 1250) * 8 + warp;
    int rowbase = t * NN;
    if (threadIdx.x < 32) smax[threadIdx.x] = 0u;
    __syncthreads();

    int sd = src[n * 32 + lane];
    float e = g_s1b[rowbase + sd] + g_s2b[rowbase + n];
    e = (e > 0.f) ? e : 0.01f * e;
    float m = e;
#pragma unroll
    for (int o = 16; o; o >>= 1) m = fmaxf(m, __shfl_xor_sync(0xffffffffu, m, o));
    float p = expf(e - m);
    float sum = p;
#pragma unroll
    for (int o = 16; o; o >>= 1) sum += __shfl_xor_sync(0xffffffffu, sum, o);
    float alpha = p / sum;

    float acc = 0.f;
#pragma unroll
    for (int d = 0; d < 32; d++) {
        float a = __shfl_sync(0xffffffffu, alpha, d);
        int s = __shfl_sync(0xffffffffu, sd, d);
        acc += a * g_z2[(size_t)(rowbase + s) * 32 + lane];
    }
    unsigned bits = __float_as_uint(fmaxf(acc, 0.f));   // >=0 => uint cmp == float cmp
    atomicMax(&smax[lane], bits);
    __syncthreads();
    if (threadIdx.x < 32)
        atomicMax((unsigned*)&g_cur[t * 32 + threadIdx.x], smax[threadIdx.x]);
}

// ---------------- sequential GRU + readout + SIR physics -------------------
__device__ __forceinline__ float sigf(float x) { return 1.0f / (1.0f + expf(-x)); }

__global__ __launch_bounds__(128) void seq_kernel(
    const float* __restrict__ Nn, const float* __restrict__ I,
    const float* __restrict__ R, const float* __restrict__ S,
    const float* __restrict__ It, const float* __restrict__ Rt,
    const float* __restrict__ hx0,
    const float* __restrict__ W_ih, const float* __restrict__ W_hh,
    const float* __restrict__ b_ih, const float* __restrict__ b_hh,
    const float* __restrict__ Wr1, const float* __restrict__ br1,
    const float* __restrict__ Wr2, const float* __restrict__ br2,
    float* __restrict__ out)
{
    __shared__ float sWih[3072], sWhh[3072];
    __shared__ float hx[34], cur[32], gi[96], gh[96], pred[12];
    int tid = threadIdx.x;
    for (int i = tid; i < 3072; i += 128) { sWih[i] = W_ih[i]; sWhh[i] = W_hh[i]; }
    if (tid < 32) hx[tid] = hx0[tid];
    float Ns = Nn[0];
    __syncthreads();

    for (int t = 0; t < T; t++) {
        if (tid < 32) cur[tid] = g_cur[t * 32 + tid];
        __syncthreads();
        if (tid < 96) {
            float a = b_ih[tid], b = b_hh[tid];
#pragma unroll
            for (int k = 0; k < 32; k++) {
                a += cur[k] * sWih[tid * 32 + k];
                b += hx[k]  * sWhh[tid * 32 + k];
            }
            gi[tid] = a; gh[tid] = b;
        }
        __syncthreads();
        float hxn = 0.f;
        if (tid < 32) {
            float r  = sigf(gi[tid]      + gh[tid]);
            float zg = sigf(gi[32 + tid] + gh[32 + tid]);
            float ng = tanhf(gi[64 + tid] + r * gh[64 + tid]);
            hxn = (1.0f - zg) * ng + zg * hx[tid];
        }
        __syncthreads();
        if (tid < 32) hx[tid] = hxn;
        if (tid == 32) hx[32] = It[t];
        if (tid == 33) hx[33] = Rt[t];
        __syncthreads();
        if (tid < 12) {
            const float* Wr = (tid < 10) ? (Wr1 + tid * 34) : (Wr2 + (tid - 10) * 34);
            float pv = (tid < 10) ? br1[tid] : br2[tid - 10];
#pragma unroll
            for (int k = 0; k < 34; k++) pv += hx[k] * Wr[k];
            pred[tid] = pv;
        }
        __syncthreads();
        if (tid < 5) {
            out[t * 5 + tid]       = pred[2 * tid];      // nI
            out[160 + t * 5 + tid] = pred[2 * tid + 1];  // nR
        }
        if (tid == 0) {
            float a_s = sigf(pred[10]);
            float b_s = sigf(pred[11]);
            float lI = I[t], lR = R[t], lS = S[t];
            float dI = 0.f, dR = 0.f;
#pragma unroll
            for (int i = 0; i < PH; i++) {
                if (i > 0) { lI += dI; lR += dR; lS = Ns - lI - lR; }
                dI = a_s * lI * (lS / Ns) - b_s * lI;
                dR = b_s * lI;
                out[320 + t * 5 + i] = dI;   // pI
                out[480 + t * 5 + i] = dR;   // pR
            }
        }
        __syncthreads();
    }
}

// ---------------- launch ---------------------------------------------------
extern "C" void kernel_launch(void* const* d_in, const int* in_sizes, int n_in,
                              void* d_out, int out_size)
{
    const float* h    = (const float*)d_in[0];
    const int*   src  = (const int*)  d_in[1];
    const float* Nn   = (const float*)d_in[2];
    const float* I    = (const float*)d_in[3];
    const float* R    = (const float*)d_in[4];
    const float* S    = (const float*)d_in[5];
    const float* It   = (const float*)d_in[6];
    const float* Rt   = (const float*)d_in[7];
    const float* hx0  = (const float*)d_in[8];
    const float* W1   = (const float*)d_in[9];
    const float* a1   = (const float*)d_in[10];
    const float* W2   = (const float*)d_in[11];
    const float* a2   = (const float*)d_in[12];
    const float* W_ih = (const float*)d_in[13];
    const float* W_hh = (const float*)d_in[14];
    const float* b_ih = (const float*)d_in[15];
    const float* b_hh = (const float*)d_in[16];
    const float* Wr1  = (const float*)d_in[17];
    const float* br1  = (const float*)d_in[18];
    const float* Wr2  = (const float*)d_in[19];
    const float* br2  = (const float*)d_in[20];
    float* out = (float*)d_out;

    zero_cur_kernel<<<1, 1024>>>();
    gemm1_kernel<<<ROWS / 128, 256>>>(h, W1, a1);
    agg1_kernel<<<(T * NN * HEADS) / 8, 256>>>(src);
    gemm2_kernel<<<ROWS / 128, 256>>>(W2, a2);
    agg2_kernel<<<(T * NN) / 8, 256>>>(src);
    seq_kernel<<<1, 128>>>(Nn, I, R, S, It, Rt, hx0, W_ih, W_hh, b_ih, b_hh,
                           Wr1, br1, Wr2, br2, out);
}

// round 7
// speedup vs baseline: 1.2441x; 1.2441x over previous
#include <cuda_runtime.h>
#include <cuda_fp16.h>
#include <cstdint>

#define T 32
#define NN 10000
#define DEG 32
#define ROWS (T*NN)          // 320000
#define HEADS 4
#define PH 5

// ---------------- scratch (device globals; no allocation allowed) ----------
__device__ __half g_z1h[(size_t)ROWS * 128];   // [row][hd*32+e], half
__device__ float  g_s1a[ROWS * 4];             // a_src . z1  per (row, head)
__device__ float  g_s2a[ROWS * 4];             // a_dst . z1
__device__ __half g_h1h[(size_t)ROWS * 128];   // relu(agg1) hi plane
__device__ __half g_h1l[(size_t)ROWS * 128];   // lo plane (exact split)
__device__ __half g_z2h[(size_t)ROWS * 32];
__device__ float  g_s1b[ROWS];
__device__ float  g_s2b[ROWS];
__device__ float  g_cur[T * 32];               // per-t feature max (>=0)

__global__ void zero_cur_kernel() {
    g_cur[threadIdx.x] = 0.0f;                 // 1024 threads = T*32
}

// ---------------- mma / ldmatrix helpers -----------------------------------
__device__ __forceinline__ void mma_16816(float d[4], const uint32_t a[4],
                                          const uint32_t b[2]) {
    asm volatile(
        "mma.sync.aligned.m16n8k16.row.col.f32.f16.f16.f32 "
        "{%0,%1,%2,%3}, {%4,%5,%6,%7}, {%8,%9}, {%0,%1,%2,%3};\n"
        : "+f"(d[0]), "+f"(d[1]), "+f"(d[2]), "+f"(d[3])
        : "r"(a[0]), "r"(a[1]), "r"(a[2]), "r"(a[3]), "r"(b[0]), "r"(b[1]));
}

__device__ __forceinline__ void ldsm_x4(uint32_t r[4], const __half* p) {
    uint32_t addr = (uint32_t)__cvta_generic_to_shared(p);
    asm volatile("ldmatrix.sync.aligned.m8n8.x4.shared.b16 {%0,%1,%2,%3}, [%4];\n"
                 : "=r"(r[0]), "=r"(r[1]), "=r"(r[2]), "=r"(r[3]) : "r"(addr));
}

__device__ __forceinline__ void ldsm_x4_t(uint32_t r[4], const __half* p) {
    uint32_t addr = (uint32_t)__cvta_generic_to_shared(p);
    asm volatile("ldmatrix.sync.aligned.m8n8.x4.trans.shared.b16 {%0,%1,%2,%3}, [%4];\n"
                 : "=r"(r[0]), "=r"(r[1]), "=r"(r[2]), "=r"(r[3]) : "r"(addr));
}

__device__ __forceinline__ void split2(float x, __half& hi, __half& lo) {
    hi = __float2half_rn(x);
    lo = __float2half_rn(x - __half2float(hi));
}

// ---------------- GEMM1: z1 = h @ W1 via split-fp16 HMMA -------------------
// Block: 128 rows, N=128 full, K staged by 32. 8 warps = 4(m) x 2(n),
// warp tile 32x64, 3-product split-fp16 (hi*hi + hi*lo + lo*hi).
__global__ __launch_bounds__(256, 1) void gemm1_mma(
    const float* __restrict__ A, const float* __restrict__ W1,
    const float* __restrict__ a1)
{
    __shared__ __half Ah[128 * 40], Al[128 * 40];   // [m][k] stride 40
    __shared__ __half Bh[32 * 136], Bl[32 * 136];   // [k][n] stride 136
    int tid = threadIdx.x, lane = tid & 31, wid = tid >> 5;
    int wm = wid >> 1, wn = wid & 1;
    int rowBase = blockIdx.x * 128;

    float d[2][8][4];
#pragma unroll
    for (int i = 0; i < 2; i++)
#pragma unroll
        for (int j = 0; j < 8; j++)
#pragma unroll
            for (int k = 0; k < 4; k++) d[i][j][k] = 0.0f;

    int r8 = (lane & 7) + ((lane >> 3) & 1) * 8;
    int s8 = (lane >> 4) * 8;

    for (int kb = 0; kb < 4; kb++) {
        // ---- stage A (128x32 fp32 -> split-half) ----
        {
            int r = tid >> 1, c0 = (tid & 1) * 16;
            const float4* s4 = (const float4*)(A + (size_t)(rowBase + r) * 128 + kb * 32 + c0);
#pragma unroll
            for (int q = 0; q < 4; q++) {
                float4 v = s4[q];
                __half h0, h1, h2, h3, l0, l1, l2, l3;
                split2(v.x, h0, l0); split2(v.y, h1, l1);
                split2(v.z, h2, l2); split2(v.w, h3, l3);
                int o = r * 40 + c0 + q * 4;
                *(__half2*)(Ah + o)     = __halves2half2(h0, h1);
                *(__half2*)(Ah + o + 2) = __halves2half2(h2, h3);
                *(__half2*)(Al + o)     = __halves2half2(l0, l1);
                *(__half2*)(Al + o + 2) = __halves2half2(l2, l3);
            }
        }
        // ---- stage B (32x128) : B[k][j] = W1[j>>5][kb*32+k][j&31] ----
        {
            int k = tid >> 3, c0 = (tid & 7) * 16;
#pragma unroll
            for (int q = 0; q < 4; q++) {
                int j = c0 + q * 4;
                float4 v = *(const float4*)(W1 + (size_t)(j >> 5) * 4096 +
                                            (size_t)(kb * 32 + k) * 32 + (j & 31));
                __half h0, h1, h2, h3, l0, l1, l2, l3;
                split2(v.x, h0, l0); split2(v.y, h1, l1);
                split2(v.z, h2, l2); split2(v.w, h3, l3);
                int o = k * 136 + j;
                *(__half2*)(Bh + o)     = __halves2half2(h0, h1);
                *(__half2*)(Bh + o + 2) = __halves2half2(h2, h3);
                *(__half2*)(Bl + o)     = __halves2half2(l0, l1);
                *(__half2*)(Bl + o + 2) = __halves2half2(l2, l3);
            }
        }
        __syncthreads();

#pragma unroll
        for (int ks = 0; ks < 2; ks++) {
            int k0 = ks * 16;
            uint32_t ah[2][4], al[2][4];
#pragma unroll
            for (int mt = 0; mt < 2; mt++) {
                int m0 = wm * 32 + mt * 16;
                const __half* pa = Ah + (m0 + r8) * 40 + k0 + s8;
                const __half* pl = Al + (m0 + r8) * 40 + k0 + s8;
                ldsm_x4(ah[mt], pa);
                ldsm_x4(al[mt], pl);
            }
            uint32_t bh[4][4], bl[4][4];
#pragma unroll
            for (int nr = 0; nr < 4; nr++) {
                int n0 = wn * 64 + nr * 16;
                const __half* pb = Bh + (k0 + r8) * 136 + n0 + s8;
                const __half* pl = Bl + (k0 + r8) * 136 + n0 + s8;
                ldsm_x4_t(bh[nr], pb);
                ldsm_x4_t(bl[nr], pl);
            }
#pragma unroll
            for (int mt = 0; mt < 2; mt++)
#pragma unroll
                for (int nt = 0; nt < 8; nt++) {
                    const uint32_t* bhp = &bh[nt >> 1][(nt & 1) * 2];
                    const uint32_t* blp = &bl[nt >> 1][(nt & 1) * 2];
                    mma_16816(d[mt][nt], ah[mt], bhp);
                    mma_16816(d[mt][nt], ah[mt], blp);
                    mma_16816(d[mt][nt], al[mt], bhp);
                }
        }
        __syncthreads();
    }

    // ---- epilogue: z1 (half) + attention score scalars (fp32) ----
    int g = lane >> 2, tq = lane & 3;
#pragma unroll
    for (int mt = 0; mt < 2; mt++) {
        int row = rowBase + wm * 32 + mt * 16 + g;
#pragma unroll
        for (int nt = 0; nt < 8; nt++) {
            int col = wn * 64 + nt * 8 + 2 * tq;
            *(__half2*)(g_z1h + (size_t)row * 128 + col) =
                __floats2half2_rn(d[mt][nt][0], d[mt][nt][1]);
            *(__half2*)(g_z1h + (size_t)(row + 8) * 128 + col) =
                __floats2half2_rn(d[mt][nt][2], d[mt][nt][3]);
        }
#pragma unroll
        for (int hl = 0; hl < 2; hl++) {
            int hd = wn * 2 + hl;
            float p1lo = 0.f, p2lo = 0.f, p1hi = 0.f, p2hi = 0.f;
#pragma unroll
            for (int ntl = 0; ntl < 4; ntl++) {
                int nt = hl * 4 + ntl;
                int e = ntl * 8 + 2 * tq;
                float w1a = a1[hd * 64 + e],      w1b = a1[hd * 64 + e + 1];
                float w2a = a1[hd * 64 + 32 + e], w2b = a1[hd * 64 + 33 + e];
                p1lo += d[mt][nt][0] * w1a + d[mt][nt][1] * w1b;
                p2lo += d[mt][nt][0] * w2a + d[mt][nt][1] * w2b;
                p1hi += d[mt][nt][2] * w1a + d[mt][nt][3] * w1b;
                p2hi += d[mt][nt][2] * w2a + d[mt][nt][3] * w2b;
            }
#pragma unroll
            for (int o = 1; o <= 2; o <<= 1) {
                p1lo += __shfl_xor_sync(0xffffffffu, p1lo, o);
                p2lo += __shfl_xor_sync(0xffffffffu, p2lo, o);
                p1hi += __shfl_xor_sync(0xffffffffu, p1hi, o);
                p2hi += __shfl_xor_sync(0xffffffffu, p2hi, o);
            }
            if (tq == 0) {
                g_s1a[(size_t)row * 4 + hd]       = p1lo;
                g_s2a[(size_t)row * 4 + hd]       = p2lo;
                g_s1a[(size_t)(row + 8) * 4 + hd] = p1hi;
                g_s2a[(size_t)(row + 8) * 4 + hd] = p2hi;
            }
        }
    }
}

// ---------------- agg1: softmax + weighted gather (half), split output -----
// warp per (t,n,head); gathers 2 neighbors/step via half2 loads.
__global__ __launch_bounds__(256) void agg1_kernel(const int* __restrict__ src)
{
    int warp = threadIdx.x >> 5, lane = threadIdx.x & 31;
    int t = blockIdx.x / 5000;
    int id = (blockIdx.x % 5000) * 8 + warp;   // 0..39999
    int n = id >> 2, hd = id & 3;
    int rowbase = t * NN;

    int sd = src[n * 32 + lane];
    float e = g_s1a[(size_t)(rowbase + sd) * 4 + hd] + g_s2a[(size_t)(rowbase + n) * 4 + hd];
    e = (e > 0.f) ? e : 0.01f * e;
    float m = e;
#pragma unroll
    for (int o = 16; o; o >>= 1) m = fmaxf(m, __shfl_xor_sync(0xffffffffu, m, o));
    float p = expf(e - m);
    float sum = p;
#pragma unroll
    for (int o = 16; o; o >>= 1) sum += __shfl_xor_sync(0xffffffffu, sum, o);
    float alpha = p / sum;

    const __half* zb = g_z1h + (size_t)rowbase * 128 + hd * 32;
    int pairIdx = lane >> 4, f2 = lane & 15;
    float ax = 0.f, ay = 0.f;
#pragma unroll
    for (int dd = 0; dd < 32; dd += 2) {
        int d2 = dd + pairIdx;
        float a = __shfl_sync(0xffffffffu, alpha, d2);
        int s   = __shfl_sync(0xffffffffu, sd, d2);
        __half2 v = *(const __half2*)(zb + (size_t)s * 128 + 2 * f2);
        float2 vf = __half22float2(v);
        ax += a * vf.x; ay += a * vf.y;
    }
    ax += __shfl_xor_sync(0xffffffffu, ax, 16);
    ay += __shfl_xor_sync(0xffffffffu, ay, 16);
    if (lane < 16) {
        float vx = fmaxf(ax, 0.f), vy = fmaxf(ay, 0.f);
        __half hx, hy, lx, ly;
        split2(vx, hx, lx); split2(vy, hy, ly);
        size_t ob = (size_t)(rowbase + n) * 128 + hd * 32 + 2 * f2;
        *(__half2*)(g_h1h + ob) = __halves2half2(hx, hy);
        *(__half2*)(g_h1l + ob) = __halves2half2(lx, ly);
    }
}

// ---------------- GEMM2: z2 = h1 @ W2 via split-fp16 HMMA (N=32) -----------
// 8 warps, each one m16 tile; K staged by 32.
__global__ __launch_bounds__(256, 1) void gemm2_mma(
    const float* __restrict__ W2, const float* __restrict__ a2)
{
    __shared__ __half Ah[128 * 40], Al[128 * 40];   // [m][k]
    __shared__ __half Bh[32 * 40],  Bl[32 * 40];    // [k][n]
    int tid = threadIdx.x, lane = tid & 31, wid = tid >> 5;
    int rowBase = blockIdx.x * 128;

    float d[4][4];
#pragma unroll
    for (int i = 0; i < 4; i++)
#pragma unroll
        for (int j = 0; j < 4; j++) d[i][j] = 0.0f;

    int r8 = (lane & 7) + ((lane >> 3) & 1) * 8;
    int s8 = (lane >> 4) * 8;

    for (int kb = 0; kb < 4; kb++) {
        // stage A (already split-half planes; straight copy)
        {
            int r = tid >> 1, c0 = (tid & 1) * 16;
            size_t gb = (size_t)(rowBase + r) * 128 + kb * 32 + c0;
#pragma unroll
            for (int q = 0; q < 2; q++) {
                *(uint4*)(Ah + r * 40 + c0 + q * 8) = *(const uint4*)(g_h1h + gb + q * 8);
                *(uint4*)(Al + r * 40 + c0 + q * 8) = *(const uint4*)(g_h1l + gb + q * 8);
            }
        }
        // stage B (32x32 fp32 -> split-half)
        {
            int k = tid >> 3, n0 = (tid & 7) * 4;
            float4 v = *(const float4*)(W2 + (size_t)(kb * 32 + k) * 32 + n0);
            __half h0, h1, h2, h3, l0, l1, l2, l3;
            split2(v.x, h0, l0); split2(v.y, h1, l1);
            split2(v.z, h2, l2); split2(v.w, h3, l3);
            int o = k * 40 + n0;
            *(__half2*)(Bh + o)     = __halves2half2(h0, h1);
            *(__half2*)(Bh + o + 2) = __halves2half2(h2, h3);
            *(__half2*)(Bl + o)     = __halves2half2(l0, l1);
            *(__half2*)(Bl + o + 2) = __halves2half2(l2, l3);
        }
        __syncthreads();

#pragma unroll
        for (int ks = 0; ks < 2; ks++) {
            int k0 = ks * 16;
            int m0 = wid * 16;
            uint32_t ah[4], al[4];
            ldsm_x4(ah, Ah + (m0 + r8) * 40 + k0 + s8);
            ldsm_x4(al, Al + (m0 + r8) * 40 + k0 + s8);
            uint32_t bh[2][4], bl[2][4];
#pragma unroll
            for (int nr = 0; nr < 2; nr++) {
                int n0 = nr * 16;
                ldsm_x4_t(bh[nr], Bh + (k0 + r8) * 40 + n0 + s8);
                ldsm_x4_t(bl[nr], Bl + (k0 + r8) * 40 + n0 + s8);
            }
#pragma unroll
            for (int nt = 0; nt < 4; nt++) {
                const uint32_t* bhp = &bh[nt >> 1][(nt & 1) * 2];
                const uint32_t* blp = &bl[nt >> 1][(nt & 1) * 2];
                mma_16816(d[nt], ah, bhp);
                mma_16816(d[nt], ah, blp);
                mma_16816(d[nt], al, bhp);
            }
        }
        __syncthreads();
    }

    // epilogue: z2 half + score scalars
    int g = lane >> 2, tq = lane & 3;
    int row = rowBase + wid * 16 + g;
    float p1lo = 0.f, p2lo = 0.f, p1hi = 0.f, p2hi = 0.f;
#pragma unroll
    for (int nt = 0; nt < 4; nt++) {
        int col = nt * 8 + 2 * tq;
        *(__half2*)(g_z2h + (size_t)row * 32 + col) =
            __floats2half2_rn(d[nt][0], d[nt][1]);
        *(__half2*)(g_z2h + (size_t)(row + 8) * 32 + col) =
            __floats2half2_rn(d[nt][2], d[nt][3]);
        float w1a = a2[col],      w1b = a2[col + 1];
        float w2a = a2[32 + col], w2b = a2[33 + col];
        p1lo += d[nt][0] * w1a + d[nt][1] * w1b;
        p2lo += d[nt][0] * w2a + d[nt][1] * w2b;
        p1hi += d[nt][2] * w1a + d[nt][3] * w1b;
        p2hi += d[nt][2] * w2a + d[nt][3] * w2b;
    }
#pragma unroll
    for (int o = 1; o <= 2; o <<= 1) {
        p1lo += __shfl_xor_sync(0xffffffffu, p1lo, o);
        p2lo += __shfl_xor_sync(0xffffffffu, p2lo, o);
        p1hi += __shfl_xor_sync(0xffffffffu, p1hi, o);
        p2hi += __shfl_xor_sync(0xffffffffu, p2hi, o);
    }
    if (tq == 0) {
        g_s1b[row]     = p1lo;  g_s2b[row]     = p2lo;
        g_s1b[row + 8] = p1hi;  g_s2b[row + 8] = p2hi;
    }
}

// ---------------- agg2: softmax gather (half) + relu + node-max ------------
__global__ __launch_bounds__(256) void agg2_kernel(const int* __restrict__ src)
{
    __shared__ unsigned smax[32];
    int warp = threadIdx.x >> 5, lane = threadIdx.x & 31;
    int t = blockIdx.x / 1250;
    int n = (blockIdx.x % 1250) * 8 + warp;
    int rowbase = t * NN;
    if (threadIdx.x < 32) smax[threadIdx.x] = 0u;
    __syncthreads();

    int sd = src[n * 32 + lane];
    float e = g_s1b[rowbase + sd] + g_s2b[rowbase + n];
    e = (e > 0.f) ? e : 0.01f * e;
    float m = e;
#pragma unroll
    for (int o = 16; o; o >>= 1) m = fmaxf(m, __shfl_xor_sync(0xffffffffu, m, o));
    float p = expf(e - m);
    float sum = p;
#pragma unroll
    for (int o = 16; o; o >>= 1) sum += __shfl_xor_sync(0xffffffffu, sum, o);
    float alpha = p / sum;

    const __half* zb = g_z2h + (size_t)rowbase * 32;
    int pairIdx = lane >> 4, f2 = lane & 15;
    float ax = 0.f, ay = 0.f;
#pragma unroll
    for (int dd = 0; dd < 32; dd += 2) {
        int d2 = dd + pairIdx;
        float a = __shfl_sync(0xffffffffu, alpha, d2);
        int s   = __shfl_sync(0xffffffffu, sd, d2);
        __half2 v = *(const __half2*)(zb + (size_t)s * 32 + 2 * f2);
        float2 vf = __half22float2(v);
        ax += a * vf.x; ay += a * vf.y;
    }
    ax += __shfl_xor_sync(0xffffffffu, ax, 16);
    ay += __shfl_xor_sync(0xffffffffu, ay, 16);
    if (lane < 16) {
        atomicMax(&smax[2 * f2],     __float_as_uint(fmaxf(ax, 0.f)));
        atomicMax(&smax[2 * f2 + 1], __float_as_uint(fmaxf(ay, 0.f)));
    }
    __syncthreads();
    if (threadIdx.x < 32)
        atomicMax((unsigned*)&g_cur[t * 32 + threadIdx.x], smax[threadIdx.x]);
}

// ---------------- sequential GRU + readout + SIR physics -------------------
__device__ __forceinline__ float sigf(float x) { return 1.0f / (1.0f + expf(-x)); }

__global__ __launch_bounds__(128) void seq_kernel(
    const float* __restrict__ Nn, const float* __restrict__ I,
    const float* __restrict__ R, const float* __restrict__ S,
    const float* __restrict__ It, const float* __restrict__ Rt,
    const float* __restrict__ hx0,
    const float* __restrict__ W_ih, const float* __restrict__ W_hh,
    const float* __restrict__ b_ih, const float* __restrict__ b_hh,
    const float* __restrict__ Wr1, const float* __restrict__ br1,
    const float* __restrict__ Wr2, const float* __restrict__ br2,
    float* __restrict__ out)
{
    __shared__ float sWih[3072], sWhh[3072];
    __shared__ float hx[34], cur[32], gi[96], gh[96], pred[12];
    int tid = threadIdx.x;
    for (int i = tid; i < 3072; i += 128) { sWih[i] = W_ih[i]; sWhh[i] = W_hh[i]; }
    if (tid < 32) hx[tid] = hx0[tid];
    float Ns = Nn[0];
    __syncthreads();

    for (int t = 0; t < T; t++) {
        if (tid < 32) cur[tid] = g_cur[t * 32 + tid];
        __syncthreads();
        if (tid < 96) {
            float a = b_ih[tid], b = b_hh[tid];
#pragma unroll
            for (int k = 0; k < 32; k++) {
                a += cur[k] * sWih[tid * 32 + k];
                b += hx[k]  * sWhh[tid * 32 + k];
            }
            gi[tid] = a; gh[tid] = b;
        }
        __syncthreads();
        float hxn = 0.f;
        if (tid < 32) {
            float r  = sigf(gi[tid]      + gh[tid]);
            float zg = sigf(gi[32 + tid] + gh[32 + tid]);
            float ng = tanhf(gi[64 + tid] + r * gh[64 + tid]);
            hxn = (1.0f - zg) * ng + zg * hx[tid];
        }
        __syncthreads();
        if (tid < 32) hx[tid] = hxn;
        if (tid == 32) hx[32] = It[t];
        if (tid == 33) hx[33] = Rt[t];
        __syncthreads();
        if (tid < 12) {
            const float* Wr = (tid < 10) ? (Wr1 + tid * 34) : (Wr2 + (tid - 10) * 34);
            float pv = (tid < 10) ? br1[tid] : br2[tid - 10];
#pragma unroll
            for (int k = 0; k < 34; k++) pv += hx[k] * Wr[k];
            pred[tid] = pv;
        }
        __syncthreads();
        if (tid < 5) {
            out[t * 5 + tid]       = pred[2 * tid];      // nI
            out[160 + t * 5 + tid] = pred[2 * tid + 1];  // nR
        }
        if (tid == 0) {
            float a_s = sigf(pred[10]);
            float b_s = sigf(pred[11]);
            float lI = I[t], lR = R[t], lS = S[t];
            float dI = 0.f, dR = 0.f;
#pragma unroll
            for (int i = 0; i < PH; i++) {
                if (i > 0) { lI += dI; lR += dR; lS = Ns - lI - lR; }
                dI = a_s * lI * (lS / Ns) - b_s * lI;
                dR = b_s * lI;
                out[320 + t * 5 + i] = dI;   // pI
                out[480 + t * 5 + i] = dR;   // pR
            }
        }
        __syncthreads();
    }
}

// ---------------- launch ---------------------------------------------------
extern "C" void kernel_launch(void* const* d_in, const int* in_sizes, int n_in,
                              void* d_out, int out_size)
{
    const float* h    = (const float*)d_in[0];
    const int*   src  = (const int*)  d_in[1];
    const float* Nn   = (const float*)d_in[2];
    const float* I    = (const float*)d_in[3];
    const float* R    = (const float*)d_in[4];
    const float* S    = (const float*)d_in[5];
    const float* It   = (const float*)d_in[6];
    const float* Rt   = (const float*)d_in[7];
    const float* hx0  = (const float*)d_in[8];
    const float* W1   = (const float*)d_in[9];
    const float* a1   = (const float*)d_in[10];
    const float* W2   = (const float*)d_in[11];
    const float* a2   = (const float*)d_in[12];
    const float* W_ih = (const float*)d_in[13];
    const float* W_hh = (const float*)d_in[14];
    const float* b_ih = (const float*)d_in[15];
    const float* b_hh = (const float*)d_in[16];
    const float* Wr1  = (const float*)d_in[17];
    const float* br1  = (const float*)d_in[18];
    const float* Wr2  = (const float*)d_in[19];
    const float* br2  = (const float*)d_in[20];
    float* out = (float*)d_out;

    zero_cur_kernel<<<1, 1024>>>();
    gemm1_mma<<<ROWS / 128, 256>>>(h, W1, a1);
    agg1_kernel<<<(T * NN * HEADS) / 8, 256>>>(src);
    gemm2_mma<<<ROWS / 128, 256>>>(W2, a2);
    agg2_kernel<<<(T * NN) / 8, 256>>>(src);
    seq_kernel<<<1, 128>>>(Nn, I, R, S, It, Rt, hx0, W_ih, W_hh, b_ih, b_hh,
                           Wr1, br1, Wr2, br2, out);
}

// round 8
// speedup vs baseline: 1.4596x; 1.1732x over previous
#include <cuda_runtime.h>
#include <cuda_fp16.h>
#include <cstdint>

#define T 32
#define NN 10000
#define DEG 32
#define ROWS (T*NN)          // 320000
#define HEADS 4
#define PH 5

// ---------------- scratch (device globals; no allocation allowed) ----------
__device__ __half g_z1h[(size_t)ROWS * 128];   // [row][hd*32+e], half
__device__ float  g_s1a[ROWS * 4];             // a_src . z1  per (row, head)
__device__ float  g_s2a[ROWS * 4];             // a_dst . z1
__device__ __half g_h1h[(size_t)ROWS * 128];   // relu(agg1) hi plane
__device__ __half g_h1l[(size_t)ROWS * 128];   // lo plane (exact split)
__device__ __half g_z2h[(size_t)ROWS * 32];
__device__ float  g_s1b[ROWS];
__device__ float  g_s2b[ROWS];
__device__ float  g_cur[T * 32];               // per-t feature max (>=0)

__global__ void zero_cur_kernel() {
    g_cur[threadIdx.x] = 0.0f;                 // 1024 threads = T*32
}

// ---------------- mma / ldmatrix helpers -----------------------------------
__device__ __forceinline__ void mma_16816(float d[4], const uint32_t a[4],
                                          const uint32_t b[2]) {
    asm volatile(
        "mma.sync.aligned.m16n8k16.row.col.f32.f16.f16.f32 "
        "{%0,%1,%2,%3}, {%4,%5,%6,%7}, {%8,%9}, {%0,%1,%2,%3};\n"
        : "+f"(d[0]), "+f"(d[1]), "+f"(d[2]), "+f"(d[3])
        : "r"(a[0]), "r"(a[1]), "r"(a[2]), "r"(a[3]), "r"(b[0]), "r"(b[1]));
}

__device__ __forceinline__ void ldsm_x4(uint32_t r[4], const __half* p) {
    uint32_t addr = (uint32_t)__cvta_generic_to_shared(p);
    asm volatile("ldmatrix.sync.aligned.m8n8.x4.shared.b16 {%0,%1,%2,%3}, [%4];\n"
                 : "=r"(r[0]), "=r"(r[1]), "=r"(r[2]), "=r"(r[3]) : "r"(addr));
}

__device__ __forceinline__ void ldsm_x4_t(uint32_t r[4], const __half* p) {
    uint32_t addr = (uint32_t)__cvta_generic_to_shared(p);
    asm volatile("ldmatrix.sync.aligned.m8n8.x4.trans.shared.b16 {%0,%1,%2,%3}, [%4];\n"
                 : "=r"(r[0]), "=r"(r[1]), "=r"(r[2]), "=r"(r[3]) : "r"(addr));
}

__device__ __forceinline__ void split2(float x, __half& hi, __half& lo) {
    hi = __float2half_rn(x);
    lo = __float2half_rn(x - __half2float(hi));
}

// ---------------- GEMM1: z1 = h @ W1 via split-fp16 HMMA -------------------
// Full B staged once (128x128 split planes), A double-buffered by K=32 chunk.
// 8 warps = 4(m) x 2(n), warp tile 32x64.
#define G1_BH    0
#define G1_BL    17408           // 128*136
#define G1_AB    34816           // A buffers: buf*10240 { Ah 5120, Al 5120 }
#define G1_SMEM  ((34816 + 20480) * 2)   // bytes = 110592

__global__ __launch_bounds__(256, 1) void gemm1_mma(
    const float* __restrict__ A, const float* __restrict__ W1,
    const float* __restrict__ a1)
{
    extern __shared__ __half sm[];
    __half* Bh = sm + G1_BH;
    __half* Bl = sm + G1_BL;
    int tid = threadIdx.x, lane = tid & 31, wid = tid >> 5;
    int wm = wid >> 1, wn = wid & 1;
    int rowBase = blockIdx.x * 128;

    // ---- stage full B (128x128) once ----
    {
        int k = tid >> 1, jh = (tid & 1) * 64;
#pragma unroll
        for (int q = 0; q < 16; q++) {
            int j = jh + q * 4;
            float4 v = *(const float4*)(W1 + (size_t)(j >> 5) * 4096 +
                                        (size_t)k * 32 + (j & 31));
            __half h0, h1, h2, h3, l0, l1, l2, l3;
            split2(v.x, h0, l0); split2(v.y, h1, l1);
            split2(v.z, h2, l2); split2(v.w, h3, l3);
            int o = k * 136 + j;
            *(__half2*)(Bh + o)     = __halves2half2(h0, h1);
            *(__half2*)(Bh + o + 2) = __halves2half2(h2, h3);
            *(__half2*)(Bl + o)     = __halves2half2(l0, l1);
            *(__half2*)(Bl + o + 2) = __halves2half2(l2, l3);
        }
    }

    float d[2][8][4];
#pragma unroll
    for (int i = 0; i < 2; i++)
#pragma unroll
        for (int j = 0; j < 8; j++)
#pragma unroll
            for (int k = 0; k < 4; k++) d[i][j][k] = 0.0f;

    int r8 = (lane & 7) + ((lane >> 3) & 1) * 8;
    int s8 = (lane >> 4) * 8;
    int ar = tid >> 1, ac0 = (tid & 1) * 16;

    float4 pf[4];
    // prefetch + store A chunk 0
    {
        const float4* s4 = (const float4*)(A + (size_t)(rowBase + ar) * 128 + ac0);
#pragma unroll
        for (int q = 0; q < 4; q++) pf[q] = s4[q];
        __half* Ah0 = sm + G1_AB;
        __half* Al0 = Ah0 + 5120;
#pragma unroll
        for (int q = 0; q < 4; q++) {
            __half h0, h1, h2, h3, l0, l1, l2, l3;
            split2(pf[q].x, h0, l0); split2(pf[q].y, h1, l1);
            split2(pf[q].z, h2, l2); split2(pf[q].w, h3, l3);
            int o = ar * 40 + ac0 + q * 4;
            *(__half2*)(Ah0 + o)     = __halves2half2(h0, h1);
            *(__half2*)(Ah0 + o + 2) = __halves2half2(h2, h3);
            *(__half2*)(Al0 + o)     = __halves2half2(l0, l1);
            *(__half2*)(Al0 + o + 2) = __halves2half2(l2, l3);
        }
    }
    __syncthreads();

    for (int kb = 0; kb < 4; kb++) {
        if (kb < 3) {
            const float4* s4 = (const float4*)(A + (size_t)(rowBase + ar) * 128 +
                                               (kb + 1) * 32 + ac0);
#pragma unroll
            for (int q = 0; q < 4; q++) pf[q] = s4[q];
        }
        const __half* AhB = sm + G1_AB + (kb & 1) * 10240;
        const __half* AlB = AhB + 5120;

#pragma unroll
        for (int ks = 0; ks < 2; ks++) {
            int ka = ks * 16;
            int kbg = kb * 32 + ks * 16;
            uint32_t ah[2][4], al[2][4];
#pragma unroll
            for (int mt = 0; mt < 2; mt++) {
                int m0 = wm * 32 + mt * 16;
                ldsm_x4(ah[mt], AhB + (m0 + r8) * 40 + ka + s8);
                ldsm_x4(al[mt], AlB + (m0 + r8) * 40 + ka + s8);
            }
            uint32_t bh[4][4], bl[4][4];
#pragma unroll
            for (int nr = 0; nr < 4; nr++) {
                int n0 = wn * 64 + nr * 16;
                ldsm_x4_t(bh[nr], Bh + (kbg + r8) * 136 + n0 + s8);
                ldsm_x4_t(bl[nr], Bl + (kbg + r8) * 136 + n0 + s8);
            }
#pragma unroll
            for (int mt = 0; mt < 2; mt++)
#pragma unroll
                for (int nt = 0; nt < 8; nt++) {
                    const uint32_t* bhp = &bh[nt >> 1][(nt & 1) * 2];
                    const uint32_t* blp = &bl[nt >> 1][(nt & 1) * 2];
                    mma_16816(d[mt][nt], ah[mt], bhp);
                    mma_16816(d[mt][nt], ah[mt], blp);
                    mma_16816(d[mt][nt], al[mt], bhp);
                }
        }
        if (kb < 3) {
            __half* AhN = sm + G1_AB + ((kb + 1) & 1) * 10240;
            __half* AlN = AhN + 5120;
#pragma unroll
            for (int q = 0; q < 4; q++) {
                __half h0, h1, h2, h3, l0, l1, l2, l3;
                split2(pf[q].x, h0, l0); split2(pf[q].y, h1, l1);
                split2(pf[q].z, h2, l2); split2(pf[q].w, h3, l3);
                int o = ar * 40 + ac0 + q * 4;
                *(__half2*)(AhN + o)     = __halves2half2(h0, h1);
                *(__half2*)(AhN + o + 2) = __halves2half2(h2, h3);
                *(__half2*)(AlN + o)     = __halves2half2(l0, l1);
                *(__half2*)(AlN + o + 2) = __halves2half2(l2, l3);
            }
        }
        __syncthreads();
    }

    // ---- epilogue: z1 (half) + attention score scalars (fp32) ----
    int g = lane >> 2, tq = lane & 3;
#pragma unroll
    for (int mt = 0; mt < 2; mt++) {
        int row = rowBase + wm * 32 + mt * 16 + g;
#pragma unroll
        for (int nt = 0; nt < 8; nt++) {
            int col = wn * 64 + nt * 8 + 2 * tq;
            *(__half2*)(g_z1h + (size_t)row * 128 + col) =
                __floats2half2_rn(d[mt][nt][0], d[mt][nt][1]);
            *(__half2*)(g_z1h + (size_t)(row + 8) * 128 + col) =
                __floats2half2_rn(d[mt][nt][2], d[mt][nt][3]);
        }
#pragma unroll
        for (int hl = 0; hl < 2; hl++) {
            int hd = wn * 2 + hl;
            float p1lo = 0.f, p2lo = 0.f, p1hi = 0.f, p2hi = 0.f;
#pragma unroll
            for (int ntl = 0; ntl < 4; ntl++) {
                int nt = hl * 4 + ntl;
                int e = ntl * 8 + 2 * tq;
                float w1a = a1[hd * 64 + e],      w1b = a1[hd * 64 + e + 1];
                float w2a = a1[hd * 64 + 32 + e], w2b = a1[hd * 64 + 33 + e];
                p1lo += d[mt][nt][0] * w1a + d[mt][nt][1] * w1b;
                p2lo += d[mt][nt][0] * w2a + d[mt][nt][1] * w2b;
                p1hi += d[mt][nt][2] * w1a + d[mt][nt][3] * w1b;
                p2hi += d[mt][nt][2] * w2a + d[mt][nt][3] * w2b;
            }
#pragma unroll
            for (int o = 1; o <= 2; o <<= 1) {
                p1lo += __shfl_xor_sync(0xffffffffu, p1lo, o);
                p2lo += __shfl_xor_sync(0xffffffffu, p2lo, o);
                p1hi += __shfl_xor_sync(0xffffffffu, p1hi, o);
                p2hi += __shfl_xor_sync(0xffffffffu, p2hi, o);
            }
            if (tq == 0) {
                g_s1a[(size_t)row * 4 + hd]       = p1lo;
                g_s2a[(size_t)row * 4 + hd]       = p2lo;
                g_s1a[(size_t)(row + 8) * 4 + hd] = p1hi;
                g_s2a[(size_t)(row + 8) * 4 + hd] = p2hi;
            }
        }
    }
}

// ---------------- agg1: warp per (t,n), all 4 heads, coalesced gather ------
__global__ __launch_bounds__(256) void agg1_kernel(const int* __restrict__ src)
{
    __shared__ float sal[8][32][4];
    __shared__ int   ssd[8][32];
    int warp = threadIdx.x >> 5, lane = threadIdx.x & 31;
    int t = blockIdx.x / 1250;                 // 1250 = NN/8
    int n = (blockIdx.x % 1250) * 8 + warp;
    int rowbase = t * NN;

    int sd = src[n * 32 + lane];
    float4 s1 = *(const float4*)(g_s1a + (size_t)(rowbase + sd) * 4);
    float4 s2 = *(const float4*)(g_s2a + (size_t)(rowbase + n) * 4);
    float e0 = s1.x + s2.x, e1 = s1.y + s2.y, e2 = s1.z + s2.z, e3 = s1.w + s2.w;
    e0 = (e0 > 0.f) ? e0 : 0.01f * e0;
    e1 = (e1 > 0.f) ? e1 : 0.01f * e1;
    e2 = (e2 > 0.f) ? e2 : 0.01f * e2;
    e3 = (e3 > 0.f) ? e3 : 0.01f * e3;

    float m0 = e0, m1 = e1, m2 = e2, m3 = e3;
#pragma unroll
    for (int o = 16; o; o >>= 1) {
        m0 = fmaxf(m0, __shfl_xor_sync(0xffffffffu, m0, o));
        m1 = fmaxf(m1, __shfl_xor_sync(0xffffffffu, m1, o));
        m2 = fmaxf(m2, __shfl_xor_sync(0xffffffffu, m2, o));
        m3 = fmaxf(m3, __shfl_xor_sync(0xffffffffu, m3, o));
    }
    float p0 = expf(e0 - m0), p1 = expf(e1 - m1), p2 = expf(e2 - m2), p3 = expf(e3 - m3);
    float q0 = p0, q1 = p1, q2 = p2, q3 = p3;
#pragma unroll
    for (int o = 16; o; o >>= 1) {
        q0 += __shfl_xor_sync(0xffffffffu, q0, o);
        q1 += __shfl_xor_sync(0xffffffffu, q1, o);
        q2 += __shfl_xor_sync(0xffffffffu, q2, o);
        q3 += __shfl_xor_sync(0xffffffffu, q3, o);
    }
    *(float4*)&sal[warp][lane][0] = make_float4(p0 / q0, p1 / q1, p2 / q2, p3 / q3);
    ssd[warp][lane] = sd;
    __syncwarp();

    const __half* zrow = g_z1h + (size_t)rowbase * 128;
    size_t obase = (size_t)(rowbase + n) * 128;
#pragma unroll
    for (int p = 0; p < 2; p++) {
        int fofs = p * 64 + 2 * lane;
        int hdl = p * 2 + (lane >> 4);          // head of my features
        float ax = 0.f, ay = 0.f;
#pragma unroll
        for (int dd = 0; dd < 32; dd++) {
            int s = ssd[warp][dd];
            float a = sal[warp][dd][hdl];
            __half2 v = *(const __half2*)(zrow + (size_t)s * 128 + fofs);
            float2 vf = __half22float2(v);
            ax += a * vf.x; ay += a * vf.y;
        }
        float vx = fmaxf(ax, 0.f), vy = fmaxf(ay, 0.f);
        __half hx, hy, lx, ly;
        split2(vx, hx, lx); split2(vy, hy, ly);
        *(__half2*)(g_h1h + obase + fofs) = __halves2half2(hx, hy);
        *(__half2*)(g_h1l + obase + fofs) = __halves2half2(lx, ly);
    }
}

// ---------------- GEMM2: z2 = h1 @ W2 via split-fp16 HMMA (N=32) -----------
// Full B staged once, A double-buffered; 2 CTAs/SM target.
#define G2_BH    0
#define G2_BL    5120            // 128*40
#define G2_AB    10240           // A buffers: buf*10240 { Ah 5120, Al 5120 }
#define G2_SMEM  ((10240 + 20480) * 2)   // bytes = 61440

__global__ __launch_bounds__(256, 2) void gemm2_mma(
    const float* __restrict__ W2, const float* __restrict__ a2)
{
    extern __shared__ __half sm[];
    __half* Bh = sm + G2_BH;
    __half* Bl = sm + G2_BL;
    int tid = threadIdx.x, lane = tid & 31, wid = tid >> 5;
    int rowBase = blockIdx.x * 128;

    // stage full B (128x32)
    {
        int k = tid >> 1, n0 = (tid & 1) * 16;
#pragma unroll
        for (int q = 0; q < 4; q++) {
            int j = n0 + q * 4;
            float4 v = *(const float4*)(W2 + (size_t)k * 32 + j);
            __half h0, h1, h2, h3, l0, l1, l2, l3;
            split2(v.x, h0, l0); split2(v.y, h1, l1);
            split2(v.z, h2, l2); split2(v.w, h3, l3);
            int o = k * 40 + j;
            *(__half2*)(Bh + o)     = __halves2half2(h0, h1);
            *(__half2*)(Bh + o + 2) = __halves2half2(h2, h3);
            *(__half2*)(Bl + o)     = __halves2half2(l0, l1);
            *(__half2*)(Bl + o + 2) = __halves2half2(l2, l3);
        }
    }

    float d[4][4];
#pragma unroll
    for (int i = 0; i < 4; i++)
#pragma unroll
        for (int j = 0; j < 4; j++) d[i][j] = 0.0f;

    int r8 = (lane & 7) + ((lane >> 3) & 1) * 8;
    int s8 = (lane >> 4) * 8;
    int ar = tid >> 1, ac0 = (tid & 1) * 16;

    uint4 pfh[2], pfl[2];
    {
        size_t gb = (size_t)(rowBase + ar) * 128 + ac0;
        pfh[0] = *(const uint4*)(g_h1h + gb);     pfh[1] = *(const uint4*)(g_h1h + gb + 8);
        pfl[0] = *(const uint4*)(g_h1l + gb);     pfl[1] = *(const uint4*)(g_h1l + gb + 8);
        __half* Ah0 = sm + G2_AB;
        __half* Al0 = Ah0 + 5120;
        *(uint4*)(Ah0 + ar * 40 + ac0)     = pfh[0];
        *(uint4*)(Ah0 + ar * 40 + ac0 + 8) = pfh[1];
        *(uint4*)(Al0 + ar * 40 + ac0)     = pfl[0];
        *(uint4*)(Al0 + ar * 40 + ac0 + 8) = pfl[1];
    }
    __syncthreads();

    for (int kb = 0; kb < 4; kb++) {
        if (kb < 3) {
            size_t gb = (size_t)(rowBase + ar) * 128 + (kb + 1) * 32 + ac0;
            pfh[0] = *(const uint4*)(g_h1h + gb);     pfh[1] = *(const uint4*)(g_h1h + gb + 8);
            pfl[0] = *(const uint4*)(g_h1l + gb);     pfl[1] = *(const uint4*)(g_h1l + gb + 8);
        }
        const __half* AhB = sm + G2_AB + (kb & 1) * 10240;
        const __half* AlB = AhB + 5120;

#pragma unroll
        for (int ks = 0; ks < 2; ks++) {
            int ka = ks * 16;
            int kbg = kb * 32 + ks * 16;
            int m0 = wid * 16;
            uint32_t ah[4], al[4];
            ldsm_x4(ah, AhB + (m0 + r8) * 40 + ka + s8);
            ldsm_x4(al, AlB + (m0 + r8) * 40 + ka + s8);
            uint32_t bh[2][4], bl[2][4];
#pragma unroll
            for (int nr = 0; nr < 2; nr++) {
                int n0 = nr * 16;
                ldsm_x4_t(bh[nr], Bh + (kbg + r8) * 40 + n0 + s8);
                ldsm_x4_t(bl[nr], Bl + (kbg + r8) * 40 + n0 + s8);
            }
#pragma unroll
            for (int nt = 0; nt < 4; nt++) {
                const uint32_t* bhp = &bh[nt >> 1][(nt & 1) * 2];
                const uint32_t* blp = &bl[nt >> 1][(nt & 1) * 2];
                mma_16816(d[nt], ah, bhp);
                mma_16816(d[nt], ah, blp);
                mma_16816(d[nt], al, bhp);
            }
        }
        if (kb < 3) {
            __half* AhN = sm + G2_AB + ((kb + 1) & 1) * 10240;
            __half* AlN = AhN + 5120;
            *(uint4*)(AhN + ar * 40 + ac0)     = pfh[0];
            *(uint4*)(AhN + ar * 40 + ac0 + 8) = pfh[1];
            *(uint4*)(AlN + ar * 40 + ac0)     = pfl[0];
            *(uint4*)(AlN + ar * 40 + ac0 + 8) = pfl[1];
        }
        __syncthreads();
    }

    // epilogue: z2 half + score scalars
    int g = lane >> 2, tq = lane & 3;
    int row = rowBase + wid * 16 + g;
    float p1lo = 0.f, p2lo = 0.f, p1hi = 0.f, p2hi = 0.f;
#pragma unroll
    for (int nt = 0; nt < 4; nt++) {
        int col = nt * 8 + 2 * tq;
        *(__half2*)(g_z2h + (size_t)row * 32 + col) =
            __floats2half2_rn(d[nt][0], d[nt][1]);
        *(__half2*)(g_z2h + (size_t)(row + 8) * 32 + col) =
            __floats2half2_rn(d[nt][2], d[nt][3]);
        float w1a = a2[col],      w1b = a2[col + 1];
        float w2a = a2[32 + col], w2b = a2[33 + col];
        p1lo += d[nt][0] * w1a + d[nt][1] * w1b;
        p2lo += d[nt][0] * w2a + d[nt][1] * w2b;
        p1hi += d[nt][2] * w1a + d[nt][3] * w1b;
        p2hi += d[nt][2] * w2a + d[nt][3] * w2b;
    }
#pragma unroll
    for (int o = 1; o <= 2; o <<= 1) {
        p1lo += __shfl_xor_sync(0xffffffffu, p1lo, o);
        p2lo += __shfl_xor_sync(0xffffffffu, p2lo, o);
        p1hi += __shfl_xor_sync(0xffffffffu, p1hi, o);
        p2hi += __shfl_xor_sync(0xffffffffu, p2hi, o);
    }
    if (tq == 0) {
        g_s1b[row]     = p1lo;  g_s2b[row]     = p2lo;
        g_s1b[row + 8] = p1hi;  g_s2b[row + 8] = p2hi;
    }
}

// ---------------- agg2: softmax gather (half) + relu + node-max ------------
__global__ __launch_bounds__(256) void agg2_kernel(const int* __restrict__ src)
{
    __shared__ unsigned smax[32];
    int warp = threadIdx.x >> 5, lane = threadIdx.x & 31;
    int t = blockIdx.x / 1250;
    int n = (blockIdx.x % 1250) * 8 + warp;
    int rowbase = t * NN;
    if (threadIdx.x < 32) smax[threadIdx.x] = 0u;
    __syncthreads();

    int sd = src[n * 32 + lane];
    float e = g_s1b[rowbase + sd] + g_s2b[rowbase + n];
    e = (e > 0.f) ? e : 0.01f * e;
    float m = e;
#pragma unroll
    for (int o = 16; o; o >>= 1) m = fmaxf(m, __shfl_xor_sync(0xffffffffu, m, o));
    float p = expf(e - m);
    float sum = p;
#pragma unroll
    for (int o = 16; o; o >>= 1) sum += __shfl_xor_sync(0xffffffffu, sum, o);
    float alpha = p / sum;

    const __half* zb = g_z2h + (size_t)rowbase * 32;
    int pairIdx = lane >> 4, f2 = lane & 15;
    float ax = 0.f, ay = 0.f;
#pragma unroll
    for (int dd = 0; dd < 32; dd += 2) {
        int d2 = dd + pairIdx;
        float a = __shfl_sync(0xffffffffu, alpha, d2);
        int s   = __shfl_sync(0xffffffffu, sd, d2);
        __half2 v = *(const __half2*)(zb + (size_t)s * 32 + 2 * f2);
        float2 vf = __half22float2(v);
        ax += a * vf.x; ay += a * vf.y;
    }
    ax += __shfl_xor_sync(0xffffffffu, ax, 16);
    ay += __shfl_xor_sync(0xffffffffu, ay, 16);
    if (lane < 16) {
        atomicMax(&smax[2 * f2],     __float_as_uint(fmaxf(ax, 0.f)));
        atomicMax(&smax[2 * f2 + 1], __float_as_uint(fmaxf(ay, 0.f)));
    }
    __syncthreads();
    if (threadIdx.x < 32)
        atomicMax((unsigned*)&g_cur[t * 32 + threadIdx.x], smax[threadIdx.x]);
}

// ---------------- sequential GRU + readout + SIR physics -------------------
__device__ __forceinline__ float sigf(float x) { return 1.0f / (1.0f + expf(-x)); }

__global__ __launch_bounds__(128) void seq_kernel(
    const float* __restrict__ Nn, const float* __restrict__ I,
    const float* __restrict__ R, const float* __restrict__ S,
    const float* __restrict__ It, const float* __restrict__ Rt,
    const float* __restrict__ hx0,
    const float* __restrict__ W_ih, const float* __restrict__ W_hh,
    const float* __restrict__ b_ih, const float* __restrict__ b_hh,
    const float* __restrict__ Wr1, const float* __restrict__ br1,
    const float* __restrict__ Wr2, const float* __restrict__ br2,
    float* __restrict__ out)
{
    __shared__ float sWih[3072], sWhh[3072];
    __shared__ float hx[34], cur[32], gi[96], gh[96], pred[12];
    int tid = threadIdx.x;
    for (int i = tid; i < 3072; i += 128) { sWih[i] = W_ih[i]; sWhh[i] = W_hh[i]; }
    if (tid < 32) hx[tid] = hx0[tid];
    float Ns = Nn[0];
    __syncthreads();

    for (int t = 0; t < T; t++) {
        if (tid < 32) cur[tid] = g_cur[t * 32 + tid];
        __syncthreads();
        if (tid < 96) {
            float a = b_ih[tid], b = b_hh[tid];
#pragma unroll
            for (int k = 0; k < 32; k++) {
                a += cur[k] * sWih[tid * 32 + k];
                b += hx[k]  * sWhh[tid * 32 + k];
            }
            gi[tid] = a; gh[tid] = b;
        }
        __syncthreads();
        float hxn = 0.f;
        if (tid < 32) {
            float r  = sigf(gi[tid]      + gh[tid]);
            float zg = sigf(gi[32 + tid] + gh[32 + tid]);
            float ng = tanhf(gi[64 + tid] + r * gh[64 + tid]);
            hxn = (1.0f - zg) * ng + zg * hx[tid];
        }
        __syncthreads();
        if (tid < 32) hx[tid] = hxn;
        if (tid == 32) hx[32] = It[t];
        if (tid == 33) hx[33] = Rt[t];
        __syncthreads();
        if (tid < 12) {
            const float* Wr = (tid < 10) ? (Wr1 + tid * 34) : (Wr2 + (tid - 10) * 34);
            float pv = (tid < 10) ? br1[tid] : br2[tid - 10];
#pragma unroll
            for (int k = 0; k < 34; k++) pv += hx[k] * Wr[k];
            pred[tid] = pv;
        }
        __syncthreads();
        if (tid < 5) {
            out[t * 5 + tid]       = pred[2 * tid];      // nI
            out[160 + t * 5 + tid] = pred[2 * tid + 1];  // nR
        }
        if (tid == 0) {
            float a_s = sigf(pred[10]);
            float b_s = sigf(pred[11]);
            float lI = I[t], lR = R[t], lS = S[t];
            float dI = 0.f, dR = 0.f;
#pragma unroll
            for (int i = 0; i < PH; i++) {
                if (i > 0) { lI += dI; lR += dR; lS = Ns - lI - lR; }
                dI = a_s * lI * (lS / Ns) - b_s * lI;
                dR = b_s * lI;
                out[320 + t * 5 + i] = dI;   // pI
                out[480 + t * 5 + i] = dR;   // pR
            }
        }
        __syncthreads();
    }
}

// ---------------- launch ---------------------------------------------------
extern "C" void kernel_launch(void* const* d_in, const int* in_sizes, int n_in,
                              void* d_out, int out_size)
{
    const float* h    = (const float*)d_in[0];
    const int*   src  = (const int*)  d_in[1];
    const float* Nn   = (const float*)d_in[2];
    const float* I    = (const float*)d_in[3];
    const float* R    = (const float*)d_in[4];
    const float* S    = (const float*)d_in[5];
    const float* It   = (const float*)d_in[6];
    const float* Rt   = (const float*)d_in[7];
    const float* hx0  = (const float*)d_in[8];
    const float* W1   = (const float*)d_in[9];
    const float* a1   = (const float*)d_in[10];
    const float* W2   = (const float*)d_in[11];
    const float* a2   = (const float*)d_in[12];
    const float* W_ih = (const float*)d_in[13];
    const float* W_hh = (const float*)d_in[14];
    const float* b_ih = (const float*)d_in[15];
    const float* b_hh = (const float*)d_in[16];
    const float* Wr1  = (const float*)d_in[17];
    const float* br1  = (const float*)d_in[18];
    const float* Wr2  = (const float*)d_in[19];
    const float* br2  = (const float*)d_in[20];
    float* out = (float*)d_out;

    cudaFuncSetAttribute(gemm1_mma, cudaFuncAttributeMaxDynamicSharedMemorySize, G1_SMEM);
    cudaFuncSetAttribute(gemm2_mma, cudaFuncAttributeMaxDynamicSharedMemorySize, G2_SMEM);

    zero_cur_kernel<<<1, 1024>>>();
    gemm1_mma<<<ROWS / 128, 256, G1_SMEM>>>(h, W1, a1);
    agg1_kernel<<<(T * NN) / 8, 256>>>(src);
    gemm2_mma<<<ROWS / 128, 256, G2_SMEM>>>(W2, a2);
    agg2_kernel<<<(T * NN) / 8, 256>>>(src);
    seq_kernel<<<1, 128>>>(Nn, I, R, S, It, Rt, hx0, W_ih, W_hh, b_ih, b_hh,
                           Wr1, br1, Wr2, br2, out);
}

// round 9
// speedup vs baseline: 1.5403x; 1.0552x over previous
#include <cuda_runtime.h>
#include <cuda_fp16.h>
#include <cstdint>

#define T 32
#define NN 10000
#define DEG 32
#define ROWS (T*NN)          // 320000
#define HEADS 4
#define PH 5

// ---------------- scratch (device globals; no allocation allowed) ----------
__device__ __half g_z1h[(size_t)ROWS * 128];   // [row][hd*32+e], half
__device__ float  g_s1a[ROWS * 4];             // a_src . z1  per (row, head)
__device__ float  g_s2a[ROWS * 4];             // a_dst . z1
__device__ __half g_z2h[(size_t)ROWS * 32];
__device__ float  g_s1b[ROWS];
__device__ float  g_s2b[ROWS];
__device__ float  g_cur[T * 32];               // per-t feature max (>=0)

__global__ void zero_cur_kernel() {
    g_cur[threadIdx.x] = 0.0f;                 // 1024 threads = T*32
}

// ---------------- mma / ldmatrix helpers -----------------------------------
__device__ __forceinline__ void mma_16816(float d[4], const uint32_t a[4],
                                          const uint32_t b[2]) {
    asm volatile(
        "mma.sync.aligned.m16n8k16.row.col.f32.f16.f16.f32 "
        "{%0,%1,%2,%3}, {%4,%5,%6,%7}, {%8,%9}, {%0,%1,%2,%3};\n"
        : "+f"(d[0]), "+f"(d[1]), "+f"(d[2]), "+f"(d[3])
        : "r"(a[0]), "r"(a[1]), "r"(a[2]), "r"(a[3]), "r"(b[0]), "r"(b[1]));
}

__device__ __forceinline__ void ldsm_x4(uint32_t r[4], const __half* p) {
    uint32_t addr = (uint32_t)__cvta_generic_to_shared(p);
    asm volatile("ldmatrix.sync.aligned.m8n8.x4.shared.b16 {%0,%1,%2,%3}, [%4];\n"
                 : "=r"(r[0]), "=r"(r[1]), "=r"(r[2]), "=r"(r[3]) : "r"(addr));
}

__device__ __forceinline__ void ldsm_x4_t(uint32_t r[4], const __half* p) {
    uint32_t addr = (uint32_t)__cvta_generic_to_shared(p);
    asm volatile("ldmatrix.sync.aligned.m8n8.x4.trans.shared.b16 {%0,%1,%2,%3}, [%4];\n"
                 : "=r"(r[0]), "=r"(r[1]), "=r"(r[2]), "=r"(r[3]) : "r"(addr));
}

__device__ __forceinline__ void split2(float x, __half& hi, __half& lo) {
    hi = __float2half_rn(x);
    lo = __float2half_rn(x - __half2float(hi));
}

// ---------------- GEMM1: z1 = h @ W1 via split-fp16 HMMA -------------------
// Full B staged once; single A buffer; 2 CTAs/SM for latency overlap.
// halves: Bh[128*136]=17408, Bl=17408, Ah[128*40]=5120, Al=5120
#define G1_BH    0
#define G1_BL    17408
#define G1_AH    34816
#define G1_AL    39936
#define G1_SMEM  (45056 * 2)     // 90112 bytes

__global__ __launch_bounds__(256, 2) void gemm1_mma(
    const float* __restrict__ A, const float* __restrict__ W1,
    const float* __restrict__ a1)
{
    extern __shared__ __half sm[];
    __half* Bh = sm + G1_BH;
    __half* Bl = sm + G1_BL;
    __half* Ah = sm + G1_AH;
    __half* Al = sm + G1_AL;
    int tid = threadIdx.x, lane = tid & 31, wid = tid >> 5;
    int wm = wid >> 1, wn = wid & 1;
    int rowBase = blockIdx.x * 128;

    // ---- stage full B (128x128) once ----
    {
        int k = tid >> 1, jh = (tid & 1) * 64;
#pragma unroll
        for (int q = 0; q < 16; q++) {
            int j = jh + q * 4;
            float4 v = *(const float4*)(W1 + (size_t)(j >> 5) * 4096 +
                                        (size_t)k * 32 + (j & 31));
            __half h0, h1, h2, h3, l0, l1, l2, l3;
            split2(v.x, h0, l0); split2(v.y, h1, l1);
            split2(v.z, h2, l2); split2(v.w, h3, l3);
            int o = k * 136 + j;
            *(__half2*)(Bh + o)     = __halves2half2(h0, h1);
            *(__half2*)(Bh + o + 2) = __halves2half2(h2, h3);
            *(__half2*)(Bl + o)     = __halves2half2(l0, l1);
            *(__half2*)(Bl + o + 2) = __halves2half2(l2, l3);
        }
    }

    float d[2][8][4];
#pragma unroll
    for (int i = 0; i < 2; i++)
#pragma unroll
        for (int j = 0; j < 8; j++)
#pragma unroll
            for (int k = 0; k < 4; k++) d[i][j][k] = 0.0f;

    int r8 = (lane & 7) + ((lane >> 3) & 1) * 8;
    int s8 = (lane >> 4) * 8;
    int ar = tid >> 1, ac0 = (tid & 1) * 16;

    for (int kb = 0; kb < 4; kb++) {
        // stage A chunk (128x32 fp32 -> split planes)
        {
            const float4* s4 = (const float4*)(A + (size_t)(rowBase + ar) * 128 +
                                               kb * 32 + ac0);
#pragma unroll
            for (int q = 0; q < 4; q++) {
                float4 v = s4[q];
                __half h0, h1, h2, h3, l0, l1, l2, l3;
                split2(v.x, h0, l0); split2(v.y, h1, l1);
                split2(v.z, h2, l2); split2(v.w, h3, l3);
                int o = ar * 40 + ac0 + q * 4;
                *(__half2*)(Ah + o)     = __halves2half2(h0, h1);
                *(__half2*)(Ah + o + 2) = __halves2half2(h2, h3);
                *(__half2*)(Al + o)     = __halves2half2(l0, l1);
                *(__half2*)(Al + o + 2) = __halves2half2(l2, l3);
            }
        }
        __syncthreads();

#pragma unroll
        for (int ks = 0; ks < 2; ks++) {
            int ka = ks * 16;
            int kbg = kb * 32 + ks * 16;
            uint32_t ah[2][4], al[2][4];
#pragma unroll
            for (int mt = 0; mt < 2; mt++) {
                int m0 = wm * 32 + mt * 16;
                ldsm_x4(ah[mt], Ah + (m0 + r8) * 40 + ka + s8);
                ldsm_x4(al[mt], Al + (m0 + r8) * 40 + ka + s8);
            }
#pragma unroll
            for (int nr = 0; nr < 4; nr++) {
                int n0 = wn * 64 + nr * 16;
                uint32_t bh[4], bl[4];
                ldsm_x4_t(bh, Bh + (kbg + r8) * 136 + n0 + s8);
                ldsm_x4_t(bl, Bl + (kbg + r8) * 136 + n0 + s8);
#pragma unroll
                for (int hf = 0; hf < 2; hf++) {
                    int nt = nr * 2 + hf;
#pragma unroll
                    for (int mt = 0; mt < 2; mt++) {
                        mma_16816(d[mt][nt], ah[mt], &bh[hf * 2]);
                        mma_16816(d[mt][nt], ah[mt], &bl[hf * 2]);
                        mma_16816(d[mt][nt], al[mt], &bh[hf * 2]);
                    }
                }
            }
        }
        __syncthreads();
    }

    // ---- epilogue: z1 (half) + attention score scalars (fp32) ----
    int g = lane >> 2, tq = lane & 3;
#pragma unroll
    for (int mt = 0; mt < 2; mt++) {
        int row = rowBase + wm * 32 + mt * 16 + g;
#pragma unroll
        for (int nt = 0; nt < 8; nt++) {
            int col = wn * 64 + nt * 8 + 2 * tq;
            *(__half2*)(g_z1h + (size_t)row * 128 + col) =
                __floats2half2_rn(d[mt][nt][0], d[mt][nt][1]);
            *(__half2*)(g_z1h + (size_t)(row + 8) * 128 + col) =
                __floats2half2_rn(d[mt][nt][2], d[mt][nt][3]);
        }
#pragma unroll
        for (int hl = 0; hl < 2; hl++) {
            int hd = wn * 2 + hl;
            float p1lo = 0.f, p2lo = 0.f, p1hi = 0.f, p2hi = 0.f;
#pragma unroll
            for (int ntl = 0; ntl < 4; ntl++) {
                int nt = hl * 4 + ntl;
                int e = ntl * 8 + 2 * tq;
                float w1a = a1[hd * 64 + e],      w1b = a1[hd * 64 + e + 1];
                float w2a = a1[hd * 64 + 32 + e], w2b = a1[hd * 64 + 33 + e];
                p1lo += d[mt][nt][0] * w1a + d[mt][nt][1] * w1b;
                p2lo += d[mt][nt][0] * w2a + d[mt][nt][1] * w2b;
                p1hi += d[mt][nt][2] * w1a + d[mt][nt][3] * w1b;
                p2hi += d[mt][nt][2] * w2a + d[mt][nt][3] * w2b;
            }
#pragma unroll
            for (int o = 1; o <= 2; o <<= 1) {
                p1lo += __shfl_xor_sync(0xffffffffu, p1lo, o);
                p2lo += __shfl_xor_sync(0xffffffffu, p2lo, o);
                p1hi += __shfl_xor_sync(0xffffffffu, p1hi, o);
                p2hi += __shfl_xor_sync(0xffffffffu, p2hi, o);
            }
            if (tq == 0) {
                g_s1a[(size_t)row * 4 + hd]       = p1lo;
                g_s2a[(size_t)row * 4 + hd]       = p2lo;
                g_s1a[(size_t)(row + 8) * 4 + hd] = p1hi;
                g_s2a[(size_t)(row + 8) * 4 + hd] = p2hi;
            }
        }
    }
}

// ---------------- FUSED agg1 + GEMM2 ---------------------------------------
// Block owns 128 rows. Phase A: per-node softmax gather -> split h1 planes in
// SMEM. Phase B: HMMA z2 = h1 @ W2 straight from SMEM. No h1 globals at all.
// halves: Ah[128*136]=17408, Al=17408, Bh[128*40]=5120, Bl=5120,
// then sal float[8*32*4] (4096B) + ssd int[8*32] (1024B)
#define F_AH    0
#define F_AL    17408
#define F_BH    34816
#define F_BL    39936
#define F_ALPHA 45056                 // half offset of float alpha region
#define F_SMEM  (45056 * 2 + 4096 + 1024)   // 95232 bytes

__global__ __launch_bounds__(256, 2) void fused_agg1_gemm2(
    const int* __restrict__ src,
    const float* __restrict__ W2, const float* __restrict__ a2)
{
    extern __shared__ __half sm[];
    __half* Ah = sm + F_AH;
    __half* Al = sm + F_AL;
    __half* Bh = sm + F_BH;
    __half* Bl = sm + F_BL;
    float*  sal = (float*)(sm + F_ALPHA);          // [8][32][4]
    int*    ssd = (int*)(sm + F_ALPHA + 2048);     // [8][32]
    int tid = threadIdx.x, lane = tid & 31, wid = tid >> 5;
    int rowBase = blockIdx.x * 128;

    // ---- stage full B (128x32) ----
    {
        int k = tid >> 1, n0 = (tid & 1) * 16;
#pragma unroll
        for (int q = 0; q < 4; q++) {
            int j = n0 + q * 4;
            float4 v = *(const float4*)(W2 + (size_t)k * 32 + j);
            __half h0, h1, h2, h3, l0, l1, l2, l3;
            split2(v.x, h0, l0); split2(v.y, h1, l1);
            split2(v.z, h2, l2); split2(v.w, h3, l3);
            int o = k * 40 + j;
            *(__half2*)(Bh + o)     = __halves2half2(h0, h1);
            *(__half2*)(Bh + o + 2) = __halves2half2(h2, h3);
            *(__half2*)(Bl + o)     = __halves2half2(l0, l1);
            *(__half2*)(Bl + o + 2) = __halves2half2(l2, l3);
        }
    }

    // ---- phase A: agg1 for this block's 128 nodes (16 per warp) ----
    float* salw = sal + wid * 128;
    int*   ssdw = ssd + wid * 32;
#pragma unroll 1
    for (int i = 0; i < 16; i++) {
        int m = wid * 16 + i;
        int row = rowBase + m;
        int t = row / NN;
        int n = row - t * NN;
        int rowbase_t = t * NN;

        int sd = src[n * 32 + lane];
        float4 s1 = *(const float4*)(g_s1a + (size_t)(rowbase_t + sd) * 4);
        float4 s2 = *(const float4*)(g_s2a + (size_t)row * 4);
        float e0 = s1.x + s2.x, e1 = s1.y + s2.y, e2 = s1.z + s2.z, e3 = s1.w + s2.w;
        e0 = (e0 > 0.f) ? e0 : 0.01f * e0;
        e1 = (e1 > 0.f) ? e1 : 0.01f * e1;
        e2 = (e2 > 0.f) ? e2 : 0.01f * e2;
        e3 = (e3 > 0.f) ? e3 : 0.01f * e3;

        float m0 = e0, m1 = e1, m2 = e2, m3 = e3;
#pragma unroll
        for (int o = 16; o; o >>= 1) {
            m0 = fmaxf(m0, __shfl_xor_sync(0xffffffffu, m0, o));
            m1 = fmaxf(m1, __shfl_xor_sync(0xffffffffu, m1, o));
            m2 = fmaxf(m2, __shfl_xor_sync(0xffffffffu, m2, o));
            m3 = fmaxf(m3, __shfl_xor_sync(0xffffffffu, m3, o));
        }
        float p0 = expf(e0 - m0), p1 = expf(e1 - m1);
        float p2 = expf(e2 - m2), p3 = expf(e3 - m3);
        float q0 = p0, q1 = p1, q2 = p2, q3 = p3;
#pragma unroll
        for (int o = 16; o; o >>= 1) {
            q0 += __shfl_xor_sync(0xffffffffu, q0, o);
            q1 += __shfl_xor_sync(0xffffffffu, q1, o);
            q2 += __shfl_xor_sync(0xffffffffu, q2, o);
            q3 += __shfl_xor_sync(0xffffffffu, q3, o);
        }
        *(float4*)(salw + lane * 4) = make_float4(p0 / q0, p1 / q1, p2 / q2, p3 / q3);
        ssdw[lane] = sd;
        __syncwarp();

        const __half* zrow = g_z1h + (size_t)rowbase_t * 128;
#pragma unroll
        for (int p = 0; p < 2; p++) {
            int fofs = p * 64 + 2 * lane;
            int hdl = p * 2 + (lane >> 4);
            float ax = 0.f, ay = 0.f;
#pragma unroll
            for (int dd = 0; dd < 32; dd++) {
                int s = ssdw[dd];
                float a = salw[dd * 4 + hdl];
                __half2 v = *(const __half2*)(zrow + (size_t)s * 128 + fofs);
                float2 vf = __half22float2(v);
                ax += a * vf.x; ay += a * vf.y;
            }
            float vx = fmaxf(ax, 0.f), vy = fmaxf(ay, 0.f);
            __half hx, hy, lx, ly;
            split2(vx, hx, lx); split2(vy, hy, ly);
            *(__half2*)(Ah + m * 136 + fofs) = __halves2half2(hx, hy);
            *(__half2*)(Al + m * 136 + fofs) = __halves2half2(lx, ly);
        }
        __syncwarp();
    }
    __syncthreads();

    // ---- phase B: z2 = h1 @ W2 (HMMA from SMEM) ----
    float d[4][4];
#pragma unroll
    for (int i = 0; i < 4; i++)
#pragma unroll
        for (int j = 0; j < 4; j++) d[i][j] = 0.0f;

    int r8 = (lane & 7) + ((lane >> 3) & 1) * 8;
    int s8 = (lane >> 4) * 8;
    int m0 = wid * 16;

#pragma unroll
    for (int kk = 0; kk < 8; kk++) {
        int ka = kk * 16;
        uint32_t ah[4], al[4];
        ldsm_x4(ah, Ah + (m0 + r8) * 136 + ka + s8);
        ldsm_x4(al, Al + (m0 + r8) * 136 + ka + s8);
#pragma unroll
        for (int nr = 0; nr < 2; nr++) {
            int n0 = nr * 16;
            uint32_t bh[4], bl[4];
            ldsm_x4_t(bh, Bh + (ka + r8) * 40 + n0 + s8);
            ldsm_x4_t(bl, Bl + (ka + r8) * 40 + n0 + s8);
#pragma unroll
            for (int hf = 0; hf < 2; hf++) {
                int nt = nr * 2 + hf;
                mma_16816(d[nt], ah, &bh[hf * 2]);
                mma_16816(d[nt], ah, &bl[hf * 2]);
                mma_16816(d[nt], al, &bh[hf * 2]);
            }
        }
    }

    // epilogue: z2 half + score scalars
    int g = lane >> 2, tq = lane & 3;
    int row = rowBase + wid * 16 + g;
    float p1lo = 0.f, p2lo = 0.f, p1hi = 0.f, p2hi = 0.f;
#pragma unroll
    for (int nt = 0; nt < 4; nt++) {
        int col = nt * 8 + 2 * tq;
        *(__half2*)(g_z2h + (size_t)row * 32 + col) =
            __floats2half2_rn(d[nt][0], d[nt][1]);
        *(__half2*)(g_z2h + (size_t)(row + 8) * 32 + col) =
            __floats2half2_rn(d[nt][2], d[nt][3]);
        float w1a = a2[col],      w1b = a2[col + 1];
        float w2a = a2[32 + col], w2b = a2[33 + col];
        p1lo += d[nt][0] * w1a + d[nt][1] * w1b;
        p2lo += d[nt][0] * w2a + d[nt][1] * w2b;
        p1hi += d[nt][2] * w1a + d[nt][3] * w1b;
        p2hi += d[nt][2] * w2a + d[nt][3] * w2b;
    }
#pragma unroll
    for (int o = 1; o <= 2; o <<= 1) {
        p1lo += __shfl_xor_sync(0xffffffffu, p1lo, o);
        p2lo += __shfl_xor_sync(0xffffffffu, p2lo, o);
        p1hi += __shfl_xor_sync(0xffffffffu, p1hi, o);
        p2hi += __shfl_xor_sync(0xffffffffu, p2hi, o);
    }
    if (tq == 0) {
        g_s1b[row]     = p1lo;  g_s2b[row]     = p2lo;
        g_s1b[row + 8] = p1hi;  g_s2b[row + 8] = p2hi;
    }
}

// ---------------- agg2: softmax gather (half) + relu + node-max ------------
__global__ __launch_bounds__(256) void agg2_kernel(const int* __restrict__ src)
{
    __shared__ unsigned smax[32];
    int warp = threadIdx.x >> 5, lane = threadIdx.x & 31;
    int t = blockIdx.x / 1250;
    int n = (blockIdx.x % 1250) * 8 + warp;
    int rowbase = t * NN;
    if (threadIdx.x < 32) smax[threadIdx.x] = 0u;
    __syncthreads();

    int sd = src[n * 32 + lane];
    float e = g_s1b[rowbase + sd] + g_s2b[rowbase + n];
    e = (e > 0.f) ? e : 0.01f * e;
    float m = e;
#pragma unroll
    for (int o = 16; o; o >>= 1) m = fmaxf(m, __shfl_xor_sync(0xffffffffu, m, o));
    float p = expf(e - m);
    float sum = p;
#pragma unroll
    for (int o = 16; o; o >>= 1) sum += __shfl_xor_sync(0xffffffffu, sum, o);
    float alpha = p / sum;

    const __half* zb = g_z2h + (size_t)rowbase * 32;
    int pairIdx = lane >> 4, f2 = lane & 15;
    float ax = 0.f, ay = 0.f;
#pragma unroll
    for (int dd = 0; dd < 32; dd += 2) {
        int d2 = dd + pairIdx;
        float a = __shfl_sync(0xffffffffu, alpha, d2);
        int s   = __shfl_sync(0xffffffffu, sd, d2);
        __half2 v = *(const __half2*)(zb + (size_t)s * 32 + 2 * f2);
        float2 vf = __half22float2(v);
        ax += a * vf.x; ay += a * vf.y;
    }
    ax += __shfl_xor_sync(0xffffffffu, ax, 16);
    ay += __shfl_xor_sync(0xffffffffu, ay, 16);
    if (lane < 16) {
        atomicMax(&smax[2 * f2],     __float_as_uint(fmaxf(ax, 0.f)));
        atomicMax(&smax[2 * f2 + 1], __float_as_uint(fmaxf(ay, 0.f)));
    }
    __syncthreads();
    if (threadIdx.x < 32)
        atomicMax((unsigned*)&g_cur[t * 32 + threadIdx.x], smax[threadIdx.x]);
}

// ---------------- sequential GRU + readout + SIR physics -------------------
__device__ __forceinline__ float sigf(float x) { return 1.0f / (1.0f + expf(-x)); }

__global__ __launch_bounds__(128) void seq_kernel(
    const float* __restrict__ Nn, const float* __restrict__ I,
    const float* __restrict__ R, const float* __restrict__ S,
    const float* __restrict__ It, const float* __restrict__ Rt,
    const float* __restrict__ hx0,
    const float* __restrict__ W_ih, const float* __restrict__ W_hh,
    const float* __restrict__ b_ih, const float* __restrict__ b_hh,
    const float* __restrict__ Wr1, const float* __restrict__ br1,
    const float* __restrict__ Wr2, const float* __restrict__ br2,
    float* __restrict__ out)
{
    __shared__ float sWih[3072], sWhh[3072];
    __shared__ float hx[34], cur[32], gi[96], gh[96], pred[12];
    int tid = threadIdx.x;
    for (int i = tid; i < 3072; i += 128) { sWih[i] = W_ih[i]; sWhh[i] = W_hh[i]; }
    if (tid < 32) hx[tid] = hx0[tid];
    float Ns = Nn[0];
    __syncthreads();

    for (int t = 0; t < T; t++) {
        if (tid < 32) cur[tid] = g_cur[t * 32 + tid];
        __syncthreads();
        if (tid < 96) {
            float a = b_ih[tid], b = b_hh[tid];
#pragma unroll
            for (int k = 0; k < 32; k++) {
                a += cur[k] * sWih[tid * 32 + k];
                b += hx[k]  * sWhh[tid * 32 + k];
            }
            gi[tid] = a; gh[tid] = b;
        }
        __syncthreads();
        float hxn = 0.f;
        if (tid < 32) {
            float r  = sigf(gi[tid]      + gh[tid]);
            float zg = sigf(gi[32 + tid] + gh[32 + tid]);
            float ng = tanhf(gi[64 + tid] + r * gh[64 + tid]);
            hxn = (1.0f - zg) * ng + zg * hx[tid];
        }
        __syncthreads();
        if (tid < 32) hx[tid] = hxn;
        if (tid == 32) hx[32] = It[t];
        if (tid == 33) hx[33] = Rt[t];
        __syncthreads();
        if (tid < 12) {
            const float* Wr = (tid < 10) ? (Wr1 + tid * 34) : (Wr2 + (tid - 10) * 34);
            float pv = (tid < 10) ? br1[tid] : br2[tid - 10];
#pragma unroll
            for (int k = 0; k < 34; k++) pv += hx[k] * Wr[k];
            pred[tid] = pv;
        }
        __syncthreads();
        if (tid < 5) {
            out[t * 5 + tid]       = pred[2 * tid];      // nI
            out[160 + t * 5 + tid] = pred[2 * tid + 1];  // nR
        }
        if (tid == 0) {
            float a_s = sigf(pred[10]);
            float b_s = sigf(pred[11]);
            float lI = I[t], lR = R[t], lS = S[t];
            float dI = 0.f, dR = 0.f;
#pragma unroll
            for (int i = 0; i < PH; i++) {
                if (i > 0) { lI += dI; lR += dR; lS = Ns - lI - lR; }
                dI = a_s * lI * (lS / Ns) - b_s * lI;
                dR = b_s * lI;
                out[320 + t * 5 + i] = dI;   // pI
                out[480 + t * 5 + i] = dR;   // pR
            }
        }
        __syncthreads();
    }
}

// ---------------- launch ---------------------------------------------------
extern "C" void kernel_launch(void* const* d_in, const int* in_sizes, int n_in,
                              void* d_out, int out_size)
{
    const float* h    = (const float*)d_in[0];
    const int*   src  = (const int*)  d_in[1];
    const float* Nn   = (const float*)d_in[2];
    const float* I    = (const float*)d_in[3];
    const float* R    = (const float*)d_in[4];
    const float* S    = (const float*)d_in[5];
    const float* It   = (const float*)d_in[6];
    const float* Rt   = (const float*)d_in[7];
    const float* hx0  = (const float*)d_in[8];
    const float* W1   = (const float*)d_in[9];
    const float* a1   = (const float*)d_in[10];
    const float* W2   = (const float*)d_in[11];
    const float* a2   = (const float*)d_in[12];
    const float* W_ih = (const float*)d_in[13];
    const float* W_hh = (const float*)d_in[14];
    const float* b_ih = (const float*)d_in[15];
    const float* b_hh = (const float*)d_in[16];
    const float* Wr1  = (const float*)d_in[17];
    const float* br1  = (const float*)d_in[18];
    const float* Wr2  = (const float*)d_in[19];
    const float* br2  = (const float*)d_in[20];
    float* out = (float*)d_out;

    cudaFuncSetAttribute(gemm1_mma, cudaFuncAttributeMaxDynamicSharedMemorySize, G1_SMEM);
    cudaFuncSetAttribute(fused_agg1_gemm2, cudaFuncAttributeMaxDynamicSharedMemorySize, F_SMEM);

    zero_cur_kernel<<<1, 1024>>>();
    gemm1_mma<<<ROWS / 128, 256, G1_SMEM>>>(h, W1, a1);
    fused_agg1_gemm2<<<ROWS / 128, 256, F_SMEM>>>(src, W2, a2);
    agg2_kernel<<<(T * NN) / 8, 256>>>(src);
    seq_kernel<<<1, 128>>>(Nn, I, R, S, It, Rt, hx0, W_ih, W_hh, b_ih, b_hh,
                           Wr1, br1, Wr2, br2, out);
}